// round 15
// baseline (speedup 1.0000x reference)
#include <cuda_runtime.h>
#include <cuda_bf16.h>
#include <math.h>

#define NB 32
#define NN 4096
#define DD 128
#define HH 64
#define KK 8
#define NCH 32          // token chunks per batch (4096/128)
#define AST 136         // gemm smem stride (bf16 elems), conflict-free

// ---------------- device scratch ----------------
__device__ __align__(16) float g_kv[(size_t)NB * NN * DD];   // [row][0..63]=k, [64..127]=v
__device__ __align__(16) float g_partU[NB * NCH * KK * HH];
__device__ __align__(16) float g_partS[NB * NCH * KK];
__device__ __align__(16) float g_slots[NB * KK * HH];
__device__ __align__(16) float g_q[NB * KK * HH];
__device__ __align__(16) uint4 g_wfrag[16 * 8 * 32];         // fragment-ordered g∘[Wk;Wv] hi/lo
__device__ __align__(16) float g_c1[128];
__device__ __align__(16) float g_c0[128];

// ---------------- helpers ----------------
__device__ __forceinline__ float d4(float4 a, float4 b) {
    return a.x * b.x + a.y * b.y + a.z * b.z + a.w * b.w;
}
__device__ __forceinline__ void fma4(float4& u, float a, float4 v) {
    u.x += a * v.x; u.y += a * v.y; u.z += a * v.z; u.w += a * v.w;
}
__device__ __forceinline__ unsigned packbf(float a, float b) {
    __nv_bfloat162 t;
    t.x = __float2bfloat16(a);
    t.y = __float2bfloat16(b);
    return *reinterpret_cast<unsigned*>(&t);
}
__device__ __forceinline__ void mma16816(float (&d)[4], const unsigned (&a)[4],
                                         unsigned b0, unsigned b1) {
    asm volatile(
        "mma.sync.aligned.m16n8k16.row.col.f32.bf16.bf16.f32 "
        "{%0,%1,%2,%3},{%4,%5,%6,%7},{%8,%9},{%0,%1,%2,%3};\n"
        : "+f"(d[0]), "+f"(d[1]), "+f"(d[2]), "+f"(d[3])
        : "r"(a[0]), "r"(a[1]), "r"(a[2]), "r"(a[3]), "r"(b0), "r"(b1));
}
__device__ __forceinline__ void ldsm4(unsigned (&r)[4], unsigned addr) {
    asm volatile("ldmatrix.sync.aligned.m8n8.x4.shared.b16 {%0,%1,%2,%3}, [%4];"
                 : "=r"(r[0]), "=r"(r[1]), "=r"(r[2]), "=r"(r[3]) : "r"(addr));
}
__device__ __forceinline__ unsigned smem_u32(const void* p) {
    unsigned a;
    asm("{ .reg .u64 t; cvta.to.shared.u64 t, %1; cvt.u32.u64 %0, t; }" : "=r"(a) : "l"(p));
    return a;
}
__device__ __forceinline__ float sigf(float x) { return 1.0f / (1.0f + expf(-x)); }

// LayerNorm over 64 elems held as (v0=idx lane, v1=idx lane+32) by one warp, eps=1e-5
__device__ __forceinline__ void ln64_reg(float& v0, float& v1,
                                         const float* __restrict__ g,
                                         const float* __restrict__ bb, int lane) {
    float s = v0 + v1, ss = v0 * v0 + v1 * v1;
#pragma unroll
    for (int o = 16; o; o >>= 1) {
        s  += __shfl_xor_sync(0xffffffffu, s,  o);
        ss += __shfl_xor_sync(0xffffffffu, ss, o);
    }
    float m  = s * (1.0f / 64.0f);
    float vv = ss * (1.0f / 64.0f) - m * m;
    float rs = rsqrtf(vv + 1e-5f);
    v0 = (v0 - m) * rs * g[lane]      + bb[lane];
    v1 = (v1 - m) * rs * g[lane + 32] + bb[lane + 32];
}

// ---------------- pack: W fragment table + c1/c0 (16 blocks) ----------------
__global__ void __launch_bounds__(256) kernel_pack(
    const float* __restrict__ Wk, const float* __restrict__ Wv,
    const float* __restrict__ ln_in_g, const float* __restrict__ ln_in_b)
{
    int tid = threadIdx.x, lane = tid & 31;
    int p = blockIdx.x * 8 + (tid >> 5);   // 0..127
    {
        const float* wrow = (p < 64) ? (Wk + p * 128) : (Wv + (size_t)(p - 64) * 128);
        float c1 = 0.f, c0 = 0.f;
#pragma unroll
        for (int i = 0; i < 4; ++i) {
            int d = lane + i * 32;
            float w = wrow[d];
            c1 += w * ln_in_g[d];
            c0 += ln_in_b[d] * w;
        }
#pragma unroll
        for (int o = 16; o; o >>= 1) {
            c1 += __shfl_xor_sync(0xffffffffu, c1, o);
            c0 += __shfl_xor_sync(0xffffffffu, c0, o);
        }
        if (lane == 0) { g_c1[p] = c1; g_c0[p] = c0; }
    }
    {
        int r2 = (p >> 3) * 8 + (lane >> 2);          // W row (output col n)
        int cc = (p & 7) * 16 + 2 * (lane & 3);       // k column base
        const float* wr = (r2 < 64) ? (Wk + r2 * 128) : (Wv + (size_t)(r2 - 64) * 128);
        float w0 = wr[cc]     * ln_in_g[cc];
        float w1 = wr[cc + 1] * ln_in_g[cc + 1];
        float w8 = wr[cc + 8] * ln_in_g[cc + 8];
        float w9 = wr[cc + 9] * ln_in_g[cc + 9];
        __nv_bfloat16 h0 = __float2bfloat16(w0), h1 = __float2bfloat16(w1);
        __nv_bfloat16 h8 = __float2bfloat16(w8), h9 = __float2bfloat16(w9);
        uint4 f;
        f.x = packbf(__bfloat162float(h0), __bfloat162float(h1));
        f.y = packbf(__bfloat162float(h8), __bfloat162float(h9));
        f.z = packbf(w0 - __bfloat162float(h0), w1 - __bfloat162float(h1));
        f.w = packbf(w8 - __bfloat162float(h8), w9 - __bfloat162float(h9));
        g_wfrag[p * 32 + lane] = f;
    }
}

// ---------------- slots init + q0 (NB blocks) ----------------
__global__ void __launch_bounds__(256) kernel_slots(
    const float* __restrict__ noise,
    const float* __restrict__ mu, const float* __restrict__ ls,
    const float* __restrict__ gsl, const float* __restrict__ bsl,
    const float* __restrict__ Wq)
{
    int tid = threadIdx.x, lane = tid & 31;
    int b = blockIdx.x;
    __shared__ float sl[512], tq[512];
    for (int idx = tid; idx < 512; idx += 256) {
        float scale = log1pf(expf(ls[idx])) + 1e-5f;   // softplus + 1e-5
        float v = mu[idx] + scale * noise[b * 512 + idx];
        sl[idx] = v;
        g_slots[b * 512 + idx] = v;
    }
    __syncthreads();
    int s = tid >> 5;
    float v0 = sl[s * 64 + lane], v1 = sl[s * 64 + lane + 32];
    ln64_reg(v0, v1, gsl, bsl, lane);
    tq[s * 64 + lane] = v0;
    tq[s * 64 + lane + 32] = v1;
    __syncwarp();
    float q0 = 0.f, q1 = 0.f;
#pragma unroll
    for (int j = 0; j < 16; ++j) {
        float4 t4 = *(const float4*)&tq[s * 64 + 4 * j];
        q0 += d4(*(const float4*)(Wq + lane * 64 + 4 * j), t4);
        q1 += d4(*(const float4*)(Wq + (lane + 32) * 64 + 4 * j), t4);
    }
    g_q[b * 512 + s * 64 + lane] = q0;
    g_q[b * 512 + s * 64 + lane + 32] = q1;
}

// ---------------- GEMM: kv = LN(x) @ [Wk;Wv]^T, ldmatrix A + fragment-table W ----------------
__global__ void __launch_bounds__(256) kernel_gemm(const float* __restrict__ x)
{
    extern __shared__ char smraw[];
    __nv_bfloat16* Ah = (__nv_bfloat16*)smraw;
    __nv_bfloat16* Al = Ah + 128 * AST;
    float* rs_s = (float*)(Al + 128 * AST);
    float* rm_s = rs_s + 128;
    float* c1s  = rm_s + 128;
    float* c0s  = c1s + 128;

    int tid = threadIdx.x, lane = tid & 31, warp = tid >> 5;
    size_t rowbase = (size_t)blockIdx.x * 128;

    for (int i = 0; i < 16; ++i) {
        int r = i * 8 + warp;
        float4 xv = *(const float4*)(x + (rowbase + r) * 128 + lane * 4);
        float s = xv.x + xv.y + xv.z + xv.w;
        float q = xv.x * xv.x + xv.y * xv.y + xv.z * xv.z + xv.w * xv.w;
#pragma unroll
        for (int o = 16; o; o >>= 1) {
            s += __shfl_xor_sync(0xffffffffu, s, o);
            q += __shfl_xor_sync(0xffffffffu, q, o);
        }
        __nv_bfloat16 h0 = __float2bfloat16(xv.x), h1 = __float2bfloat16(xv.y);
        __nv_bfloat16 h2 = __float2bfloat16(xv.z), h3 = __float2bfloat16(xv.w);
        *(unsigned*)(Ah + r * AST + lane * 4)     = packbf(xv.x, xv.y);
        *(unsigned*)(Ah + r * AST + lane * 4 + 2) = packbf(xv.z, xv.w);
        *(unsigned*)(Al + r * AST + lane * 4)     =
            packbf(xv.x - __bfloat162float(h0), xv.y - __bfloat162float(h1));
        *(unsigned*)(Al + r * AST + lane * 4 + 2) =
            packbf(xv.z - __bfloat162float(h2), xv.w - __bfloat162float(h3));
        if (lane == 0) {
            float m  = s * (1.0f / 128.0f);
            float vv = q * (1.0f / 128.0f) - m * m;
            float rv = rsqrtf(vv + 1e-5f);
            rs_s[r] = rv;
            rm_s[r] = -rv * m;
        }
    }
    if (tid < 128) { c1s[tid] = g_c1[tid]; c0s[tid] = g_c0[tid]; }
    __syncthreads();

    float acc[16][4];
#pragma unroll
    for (int nt = 0; nt < 16; ++nt)
#pragma unroll
        for (int j = 0; j < 4; ++j) acc[nt][j] = 0.f;

    const int l4 = lane >> 2, lm = lane & 3;
    const int R = warp * 16;
    unsigned ah_addr = smem_u32(Ah) + ((R + (lane & 15)) * AST + (lane >> 4) * 8) * 2;
    unsigned al_addr = ah_addr + 128 * AST * 2;

#pragma unroll
    for (int ks = 0; ks < 8; ++ks) {
        unsigned ah[4], al[4];
        ldsm4(ah, ah_addr + ks * 32);
        ldsm4(al, al_addr + ks * 32);
        const uint4* wf = g_wfrag + ks * 32 + lane;
#pragma unroll
        for (int nt = 0; nt < 16; ++nt) {
            uint4 f = wf[nt * 256];
            mma16816(acc[nt], ah, f.x, f.y);
            mma16816(acc[nt], al, f.x, f.y);
            mma16816(acc[nt], ah, f.z, f.w);
        }
    }
    int r0 = R + l4, r1 = r0 + 8;
    float rv0 = rs_s[r0], rm0 = rm_s[r0];
    float rv1 = rs_s[r1], rm1 = rm_s[r1];
    float* out0 = g_kv + (rowbase + r0) * 128;
    float* out1 = g_kv + (rowbase + r1) * 128;
#pragma unroll
    for (int nt = 0; nt < 16; ++nt) {
        int c = nt * 8 + 2 * lm;
        float2 o0, o1;
        o0.x = rv0 * acc[nt][0] + rm0 * c1s[c]     + c0s[c];
        o0.y = rv0 * acc[nt][1] + rm0 * c1s[c + 1] + c0s[c + 1];
        o1.x = rv1 * acc[nt][2] + rm1 * c1s[c]     + c0s[c];
        o1.y = rv1 * acc[nt][3] + rm1 * c1s[c + 1] + c0s[c + 1];
        *(float2*)(out0 + c) = o0;
        *(float2*)(out1 + c) = o1;
    }
}

// ---------------- attention: direct-global k/v, q in smem, dedup ----------------
__global__ void __launch_bounds__(256, 3) kernel_attn()
{
    __shared__ float redU[16 * 512];   // 32KB
    __shared__ float redS[64];
    __shared__ float q_s[512];

    int tid = threadIdx.x, lane = tid & 31, warp = tid >> 5;
    int b = blockIdx.y, ch = blockIdx.x;
    const float* kv = g_kv + ((size_t)b * NN + ch * 128) * 128;

    const int tl = lane >> 3, c = lane & 7;   // token-in-group, col-segment/slot
    const int c8  = c * 8;
    const int hh  = tl >> 1;
    const int sgb = (tl & 1) * 4;

    // stage q in smem (broadcast-read later)
    for (int idx = tid; idx < 512; idx += 256)
        q_s[idx] = g_q[b * 512 + idx];
    __syncthreads();

    float4 U4[4][2];
#pragma unroll
    for (int j = 0; j < 4; ++j) {
        U4[j][0] = make_float4(0.f, 0.f, 0.f, 0.f);
        U4[j][1] = make_float4(0.f, 0.f, 0.f, 0.f);
    }
    float sacc = 0.f;

    for (int rd = 0; rd < 4; ++rd) {
        int tb = warp * 16 + rd * 4;

        // scores: own k segment direct from global (coalesced, L2/DRAM)
        const float* kp = kv + (tb + tl) * 128 + c8;
        float4 k0 = *(const float4*)(kp);
        float4 k1 = *(const float4*)(kp + 4);
        float part[8];
#pragma unroll
        for (int si = 0; si < 8; ++si) {
            float4 q0 = *(const float4*)(q_s + si * 64 + c8);
            float4 q1 = *(const float4*)(q_s + si * 64 + c8 + 4);
            part[si] = d4(k0, q0) + d4(k1, q1);
        }
        float p2[4];
#pragma unroll
        for (int i = 0; i < 4; ++i) {
            float send = (c & 4) ? part[i] : part[4 + i];
            float keep = (c & 4) ? part[4 + i] : part[i];
            p2[i] = keep + __shfl_xor_sync(0xffffffffu, send, 4);
        }
        float p3[2];
#pragma unroll
        for (int i = 0; i < 2; ++i) {
            float send = (c & 2) ? p2[i] : p2[2 + i];
            float keep = (c & 2) ? p2[2 + i] : p2[i];
            p3[i] = keep + __shfl_xor_sync(0xffffffffu, send, 2);
        }
        float sc;
        {
            float send = (c & 1) ? p3[0] : p3[1];
            float keep = (c & 1) ? p3[1] : p3[0];
            sc = keep + __shfl_xor_sync(0xffffffffu, send, 1);
        }
        sc *= 0.125f;  // H^-0.5

        float mx = sc;
        mx = fmaxf(mx, __shfl_xor_sync(0xffffffffu, mx, 1));
        mx = fmaxf(mx, __shfl_xor_sync(0xffffffffu, mx, 2));
        mx = fmaxf(mx, __shfl_xor_sync(0xffffffffu, mx, 4));
        float e  = expf(sc - mx);
        float se = e;
        se += __shfl_xor_sync(0xffffffffu, se, 1);
        se += __shfl_xor_sync(0xffffffffu, se, 2);
        se += __shfl_xor_sync(0xffffffffu, se, 4);
        float at = e / se + 1e-8f;   // attn[tb+tl][slot c]
        sacc += at;

        // dedup update: v direct from global (offset 64 in row)
#pragma unroll
        for (int tt2 = 0; tt2 < 2; ++tt2) {
            int tloc = 2 * hh + tt2;
            float a0 = __shfl_sync(0xffffffffu, at, (tloc << 3) + sgb + 0);
            float a1 = __shfl_sync(0xffffffffu, at, (tloc << 3) + sgb + 1);
            float a2 = __shfl_sync(0xffffffffu, at, (tloc << 3) + sgb + 2);
            float a3 = __shfl_sync(0xffffffffu, at, (tloc << 3) + sgb + 3);
            const float* vp = kv + (tb + tloc) * 128 + 64 + c8;
            float4 v0 = *(const float4*)(vp);
            float4 v1 = *(const float4*)(vp + 4);
            fma4(U4[0][0], a0, v0); fma4(U4[0][1], a0, v1);
            fma4(U4[1][0], a1, v0); fma4(U4[1][1], a1, v1);
            fma4(U4[2][0], a2, v0); fma4(U4[2][1], a2, v1);
            fma4(U4[3][0], a3, v0); fma4(U4[3][1], a3, v1);
        }
    }
    {
        float* ru = redU + (warp * 2 + hh) * 512;
#pragma unroll
        for (int j = 0; j < 4; ++j) {
            *(float4*)(ru + (sgb + j) * 64 + c8)     = U4[j][0];
            *(float4*)(ru + (sgb + j) * 64 + c8 + 4) = U4[j][1];
        }
    }
    sacc += __shfl_xor_sync(0xffffffffu, sacc, 8);
    sacc += __shfl_xor_sync(0xffffffffu, sacc, 16);
    if (tl == 0) redS[warp * 8 + c] = sacc;
    __syncthreads();

    int obase = b * NCH + ch;
    for (int idx = tid; idx < 512; idx += 256) {
        float t = 0.f;
#pragma unroll
        for (int w = 0; w < 16; ++w) t += redU[w * 512 + idx];
        g_partU[obase * 512 + idx] = t;
    }
    if (tid < 8) {
        float t = 0.f;
#pragma unroll
        for (int w = 0; w < 8; ++w) t += redS[w * 8 + tid];
        g_partS[obase * 8 + tid] = t;
    }
}

// ---------------- finalize: block per (batch, slot-pair), 256 threads ----------------
__global__ void __launch_bounds__(256) kernel_final(
    const float* __restrict__ wih, const float* __restrict__ whh,
    const float* __restrict__ bih, const float* __restrict__ bhh,
    const float* __restrict__ w1,  const float* __restrict__ b1,
    const float* __restrict__ w2,  const float* __restrict__ b2,
    const float* __restrict__ gml, const float* __restrict__ bml,
    const float* __restrict__ gsl, const float* __restrict__ bsl,
    const float* __restrict__ Wq, float* __restrict__ out, int last)
{
    __shared__ float red[256];
    __shared__ float sm_u[128], sm_h[128];   // [sl][64]
    __shared__ float sm_g[768];              // [gate_row][sl]
    __shared__ float sm_t[128];
    __shared__ float sm_hid[256];            // [sl][128]
    __shared__ float sm_ns[128];
    __shared__ float sm_S[2];

    const int t = threadIdx.x, lane = t & 31, warp = t >> 5;
    const int blk = blockIdx.x, b = blk >> 2, s0 = (blk & 3) * 2;   // slots s0, s0+1

    {
        int e = t & 127, half = t >> 7;
        int sl = e >> 6, h = e & 63;
        const float* pu = g_partU + (size_t)b * NCH * 512 + (s0 + sl) * 64 + h;
        float acc = 0.f;
#pragma unroll
        for (int cc = 0; cc < 16; ++cc) acc += pu[(half * 16 + cc) * 512];
        red[t] = acc;
    }
    if (warp < 2) {
        float sv = g_partS[(b * NCH + lane) * 8 + s0 + warp];
#pragma unroll
        for (int o = 16; o; o >>= 1) sv += __shfl_xor_sync(0xffffffffu, sv, o);
        if (lane == 0) sm_S[warp] = sv;
    }
    __syncthreads();
    if (t < 128) {
        float U = red[t] + red[t + 128];
        sm_u[t] = U / sm_S[t >> 6];
        sm_h[t] = g_slots[b * 512 + (s0 + (t >> 6)) * 64 + (t & 63)];
    }
    __syncthreads();

#pragma unroll
    for (int rep = 0; rep < 2; ++rep) {
        int row = t + rep * 256;
        if (rep == 1 && t >= 128) break;
        const float* wrow = (row < 192) ? (wih + row * 64) : (whh + (size_t)(row - 192) * 64);
        const float* inp  = (row < 192) ? sm_u : sm_h;
        float bias = (row < 192) ? bih[row] : bhh[row - 192];
        float a0 = bias, a1 = bias;
#pragma unroll
        for (int j = 0; j < 16; ++j) {
            float4 w = *(const float4*)(wrow + 4 * j);
            a0 += d4(w, *(const float4*)(inp + 4 * j));
            a1 += d4(w, *(const float4*)(inp + 64 + 4 * j));
        }
        sm_g[row * 2 + 0] = a0;
        sm_g[row * 2 + 1] = a1;
    }
    __syncthreads();

    if (t < 128) {
        int sl = t >> 6, h = t & 63;
        float r = sigf(sm_g[h * 2 + sl]         + sm_g[(192 + h) * 2 + sl]);
        float z = sigf(sm_g[(64 + h) * 2 + sl]  + sm_g[(256 + h) * 2 + sl]);
        float n = tanhf(sm_g[(128 + h) * 2 + sl] + r * sm_g[(320 + h) * 2 + sl]);
        sm_ns[t] = (1.f - z) * n + z * sm_h[t];
    }
    __syncthreads();
    if (warp < 2) {
        float v0 = sm_ns[warp * 64 + lane], v1 = sm_ns[warp * 64 + lane + 32];
        ln64_reg(v0, v1, gml, bml, lane);
        sm_t[warp * 64 + lane] = v0;
        sm_t[warp * 64 + lane + 32] = v1;
    }
    __syncthreads();

    if (t < 128) {
        float a0 = b1[t], a1 = a0;
        const float* wrow = w1 + t * 64;
#pragma unroll
        for (int j = 0; j < 16; ++j) {
            float4 w = *(const float4*)(wrow + 4 * j);
            a0 += d4(w, *(const float4*)(sm_t + 4 * j));
            a1 += d4(w, *(const float4*)(sm_t + 64 + 4 * j));
        }
        sm_hid[t]       = fmaxf(a0, 0.f);
        sm_hid[128 + t] = fmaxf(a1, 0.f);
    }
    __syncthreads();

    if (t < 128) {
        int row = t >> 1, half = t & 1;
        float a0 = half ? 0.f : b2[row], a1 = a0;
        const float* wrow = w2 + row * 128 + half * 64;
        const float* i0 = sm_hid + half * 64;
        const float* i1 = sm_hid + 128 + half * 64;
#pragma unroll
        for (int j = 0; j < 16; ++j) {
            float4 w = *(const float4*)(wrow + 4 * j);
            a0 += d4(w, *(const float4*)(i0 + 4 * j));
            a1 += d4(w, *(const float4*)(i1 + 4 * j));
        }
        a0 += __shfl_xor_sync(0xffffffffu, a0, 1);
        a1 += __shfl_xor_sync(0xffffffffu, a1, 1);
        if (!half) {
            float n0 = sm_t[row] + a0;
            float n1 = sm_t[64 + row] + a1;
            g_slots[b * 512 + s0 * 64 + row] = n0;
            g_slots[b * 512 + (s0 + 1) * 64 + row] = n1;
            if (last) {
                out[b * 512 + s0 * 64 + row] = n0;
                out[b * 512 + (s0 + 1) * 64 + row] = n1;
            }
            sm_ns[row] = n0;
            sm_ns[64 + row] = n1;
        }
    }
    __syncthreads();
    if (!last) {
        if (warp < 2) {
            float v0 = sm_ns[warp * 64 + lane], v1 = sm_ns[warp * 64 + lane + 32];
            ln64_reg(v0, v1, gsl, bsl, lane);
            sm_t[warp * 64 + lane] = v0;
            sm_t[warp * 64 + lane + 32] = v1;
        }
        __syncthreads();
        if (t < 128) {
            int row = t >> 1, half = t & 1;
            float a0 = 0.f, a1 = 0.f;
            const float* wrow = Wq + row * 64 + half * 32;
#pragma unroll
            for (int j = 0; j < 8; ++j) {
                float4 w = *(const float4*)(wrow + 4 * j);
                a0 += d4(w, *(const float4*)(sm_t + half * 32 + 4 * j));
                a1 += d4(w, *(const float4*)(sm_t + 64 + half * 32 + 4 * j));
            }
            a0 += __shfl_xor_sync(0xffffffffu, a0, 1);
            a1 += __shfl_xor_sync(0xffffffffu, a1, 1);
            if (!half) {
                g_q[b * 512 + s0 * 64 + row] = a0;
                g_q[b * 512 + (s0 + 1) * 64 + row] = a1;
            }
        }
    }
}

// ---------------- launch ----------------
extern "C" void kernel_launch(void* const* d_in, const int* in_sizes, int n_in,
                              void* d_out, int out_size)
{
    const float* x       = (const float*)d_in[0];
    const float* noise   = (const float*)d_in[1];
    const float* Wq      = (const float*)d_in[2];
    const float* Wk      = (const float*)d_in[3];
    const float* Wv      = (const float*)d_in[4];
    const float* ln_in_g = (const float*)d_in[5];
    const float* ln_in_b = (const float*)d_in[6];
    const float* ln_sl_g = (const float*)d_in[7];
    const float* ln_sl_b = (const float*)d_in[8];
    const float* ln_ml_g = (const float*)d_in[9];
    const float* ln_ml_b = (const float*)d_in[10];
    const float* gru_wih = (const float*)d_in[11];
    const float* gru_whh = (const float*)d_in[12];
    const float* gru_bih = (const float*)d_in[13];
    const float* gru_bhh = (const float*)d_in[14];
    const float* mlp_w1  = (const float*)d_in[15];
    const float* mlp_b1  = (const float*)d_in[16];
    const float* mlp_w2  = (const float*)d_in[17];
    const float* mlp_b2  = (const float*)d_in[18];
    const float* mu      = (const float*)d_in[19];
    const float* ls      = (const float*)d_in[20];
    float* out = (float*)d_out;

    const int gemm_smem = 2 * 128 * AST * 2 + 4 * 128 * 4;                // 71680 B
    cudaFuncSetAttribute(kernel_gemm, cudaFuncAttributeMaxDynamicSharedMemorySize, gemm_smem);

    kernel_pack<<<16, 256>>>(Wk, Wv, ln_in_g, ln_in_b);
    kernel_slots<<<NB, 256>>>(noise, mu, ls, ln_sl_g, ln_sl_b, Wq);
    kernel_gemm<<<(NB * NN) / 128, 256, gemm_smem>>>(x);
    for (int it = 0; it < 3; ++it) {
        kernel_attn<<<dim3(NCH, NB), 256>>>();
        kernel_final<<<NB * 4, 256>>>(gru_wih, gru_whh, gru_bih, gru_bhh,
                                      mlp_w1, mlp_b1, mlp_w2, mlp_b2,
                                      ln_ml_g, ln_ml_b, ln_sl_g, ln_sl_b,
                                      Wq, out, it == 2 ? 1 : 0);
    }
}

// round 16
// speedup vs baseline: 1.4319x; 1.4319x over previous
#include <cuda_runtime.h>
#include <cuda_bf16.h>
#include <math.h>

#define NB 32
#define NN 4096
#define DD 128
#define HH 64
#define KK 8
#define NCH 32          // token chunks per batch (4096/128)
#define AST 136         // gemm smem stride (bf16 elems), conflict-free

// ---------------- device scratch ----------------
__device__ __align__(16) float g_kv[(size_t)NB * NN * DD];   // [row][0..63]=k, [64..127]=v
__device__ __align__(16) float g_partU[NB * NCH * KK * HH];
__device__ __align__(16) float g_partS[NB * NCH * KK];
__device__ __align__(16) float g_slots[NB * KK * HH];
__device__ __align__(16) float g_q[NB * KK * HH];
__device__ __align__(16) uint4 g_wfrag[16 * 8 * 32];         // fragment-ordered g∘[Wk;Wv] hi/lo
__device__ __align__(16) float g_c1[128];
__device__ __align__(16) float g_c0[128];

// ---------------- helpers ----------------
__device__ __forceinline__ float d4(float4 a, float4 b) {
    return a.x * b.x + a.y * b.y + a.z * b.z + a.w * b.w;
}
__device__ __forceinline__ void fma4(float4& u, float a, float4 v) {
    u.x += a * v.x; u.y += a * v.y; u.z += a * v.z; u.w += a * v.w;
}
__device__ __forceinline__ unsigned packbf(float a, float b) {
    __nv_bfloat162 t;
    t.x = __float2bfloat16(a);
    t.y = __float2bfloat16(b);
    return *reinterpret_cast<unsigned*>(&t);
}
__device__ __forceinline__ void mma16816(float (&d)[4], const unsigned (&a)[4],
                                         unsigned b0, unsigned b1) {
    asm volatile(
        "mma.sync.aligned.m16n8k16.row.col.f32.bf16.bf16.f32 "
        "{%0,%1,%2,%3},{%4,%5,%6,%7},{%8,%9},{%0,%1,%2,%3};\n"
        : "+f"(d[0]), "+f"(d[1]), "+f"(d[2]), "+f"(d[3])
        : "r"(a[0]), "r"(a[1]), "r"(a[2]), "r"(a[3]), "r"(b0), "r"(b1));
}
__device__ __forceinline__ void ldsm4(unsigned (&r)[4], unsigned addr) {
    asm volatile("ldmatrix.sync.aligned.m8n8.x4.shared.b16 {%0,%1,%2,%3}, [%4];"
                 : "=r"(r[0]), "=r"(r[1]), "=r"(r[2]), "=r"(r[3]) : "r"(addr));
}
__device__ __forceinline__ unsigned smem_u32(const void* p) {
    unsigned a;
    asm("{ .reg .u64 t; cvta.to.shared.u64 t, %1; cvt.u32.u64 %0, t; }" : "=r"(a) : "l"(p));
    return a;
}
__device__ __forceinline__ float sigf(float x) { return 1.0f / (1.0f + expf(-x)); }

// LayerNorm over 64 elems held as (v0=idx lane, v1=idx lane+32) by one warp, eps=1e-5
__device__ __forceinline__ void ln64_reg(float& v0, float& v1,
                                         const float* __restrict__ g,
                                         const float* __restrict__ bb, int lane) {
    float s = v0 + v1, ss = v0 * v0 + v1 * v1;
#pragma unroll
    for (int o = 16; o; o >>= 1) {
        s  += __shfl_xor_sync(0xffffffffu, s,  o);
        ss += __shfl_xor_sync(0xffffffffu, ss, o);
    }
    float m  = s * (1.0f / 64.0f);
    float vv = ss * (1.0f / 64.0f) - m * m;
    float rs = rsqrtf(vv + 1e-5f);
    v0 = (v0 - m) * rs * g[lane]      + bb[lane];
    v1 = (v1 - m) * rs * g[lane + 32] + bb[lane + 32];
}

// ---------------- pack: W fragment table + c1/c0 (4 launches x 4 blocks) ----------------
__global__ void __launch_bounds__(256) kernel_pack(
    const float* __restrict__ Wk, const float* __restrict__ Wv,
    const float* __restrict__ ln_in_g, const float* __restrict__ ln_in_b, int boff)
{
    int tid = threadIdx.x, lane = tid & 31;
    int p = (blockIdx.x + boff) * 8 + (tid >> 5);   // 0..127
    {
        const float* wrow = (p < 64) ? (Wk + p * 128) : (Wv + (size_t)(p - 64) * 128);
        float c1 = 0.f, c0 = 0.f;
#pragma unroll
        for (int i = 0; i < 4; ++i) {
            int d = lane + i * 32;
            float w = wrow[d];
            c1 += w * ln_in_g[d];
            c0 += ln_in_b[d] * w;
        }
#pragma unroll
        for (int o = 16; o; o >>= 1) {
            c1 += __shfl_xor_sync(0xffffffffu, c1, o);
            c0 += __shfl_xor_sync(0xffffffffu, c0, o);
        }
        if (lane == 0) { g_c1[p] = c1; g_c0[p] = c0; }
    }
    {
        int r2 = (p >> 3) * 8 + (lane >> 2);          // W row (output col n)
        int cc = (p & 7) * 16 + 2 * (lane & 3);       // k column base
        const float* wr = (r2 < 64) ? (Wk + r2 * 128) : (Wv + (size_t)(r2 - 64) * 128);
        float w0 = wr[cc]     * ln_in_g[cc];
        float w1 = wr[cc + 1] * ln_in_g[cc + 1];
        float w8 = wr[cc + 8] * ln_in_g[cc + 8];
        float w9 = wr[cc + 9] * ln_in_g[cc + 9];
        __nv_bfloat16 h0 = __float2bfloat16(w0), h1 = __float2bfloat16(w1);
        __nv_bfloat16 h8 = __float2bfloat16(w8), h9 = __float2bfloat16(w9);
        uint4 f;
        f.x = packbf(__bfloat162float(h0), __bfloat162float(h1));
        f.y = packbf(__bfloat162float(h8), __bfloat162float(h9));
        f.z = packbf(w0 - __bfloat162float(h0), w1 - __bfloat162float(h1));
        f.w = packbf(w8 - __bfloat162float(h8), w9 - __bfloat162float(h9));
        g_wfrag[p * 32 + lane] = f;
    }
}

// ---------------- slots init + q0 (NB blocks) ----------------
__global__ void __launch_bounds__(256) kernel_slots(
    const float* __restrict__ noise,
    const float* __restrict__ mu, const float* __restrict__ ls,
    const float* __restrict__ gsl, const float* __restrict__ bsl,
    const float* __restrict__ Wq)
{
    int tid = threadIdx.x, lane = tid & 31;
    int b = blockIdx.x;
    __shared__ float sl[512], tq[512];
    for (int idx = tid; idx < 512; idx += 256) {
        float scale = log1pf(expf(ls[idx])) + 1e-5f;   // softplus + 1e-5
        float v = mu[idx] + scale * noise[b * 512 + idx];
        sl[idx] = v;
        g_slots[b * 512 + idx] = v;
    }
    __syncthreads();
    int s = tid >> 5;
    float v0 = sl[s * 64 + lane], v1 = sl[s * 64 + lane + 32];
    ln64_reg(v0, v1, gsl, bsl, lane);
    tq[s * 64 + lane] = v0;
    tq[s * 64 + lane + 32] = v1;
    __syncwarp();
    float q0 = 0.f, q1 = 0.f;
#pragma unroll
    for (int j = 0; j < 16; ++j) {
        float4 t4 = *(const float4*)&tq[s * 64 + 4 * j];
        q0 += d4(*(const float4*)(Wq + lane * 64 + 4 * j), t4);
        q1 += d4(*(const float4*)(Wq + (lane + 32) * 64 + 4 * j), t4);
    }
    g_q[b * 512 + s * 64 + lane] = q0;
    g_q[b * 512 + s * 64 + lane + 32] = q1;
}

// ---------------- GEMM: BM=64 tile, warp-split-N, ldmatrix A + fragment-table W ----------------
__global__ void __launch_bounds__(256) kernel_gemm(const float* __restrict__ x)
{
    __shared__ __nv_bfloat16 Ah[64 * AST];
    __shared__ __nv_bfloat16 Al[64 * AST];
    __shared__ float rs_s[64], rm_s[64], c1s[128], c0s[128];

    int tid = threadIdx.x, lane = tid & 31, warp = tid >> 5;
    size_t rowbase = (size_t)blockIdx.x * 64;

    // load x tile (64 rows), per-row stats, bf16 hi/lo split
    for (int i = 0; i < 8; ++i) {
        int r = i * 8 + warp;
        float4 xv = *(const float4*)(x + (rowbase + r) * 128 + lane * 4);
        float s = xv.x + xv.y + xv.z + xv.w;
        float q = xv.x * xv.x + xv.y * xv.y + xv.z * xv.z + xv.w * xv.w;
#pragma unroll
        for (int o = 16; o; o >>= 1) {
            s += __shfl_xor_sync(0xffffffffu, s, o);
            q += __shfl_xor_sync(0xffffffffu, q, o);
        }
        __nv_bfloat16 h0 = __float2bfloat16(xv.x), h1 = __float2bfloat16(xv.y);
        __nv_bfloat16 h2 = __float2bfloat16(xv.z), h3 = __float2bfloat16(xv.w);
        *(unsigned*)(Ah + r * AST + lane * 4)     = packbf(xv.x, xv.y);
        *(unsigned*)(Ah + r * AST + lane * 4 + 2) = packbf(xv.z, xv.w);
        *(unsigned*)(Al + r * AST + lane * 4)     =
            packbf(xv.x - __bfloat162float(h0), xv.y - __bfloat162float(h1));
        *(unsigned*)(Al + r * AST + lane * 4 + 2) =
            packbf(xv.z - __bfloat162float(h2), xv.w - __bfloat162float(h3));
        if (lane == 0) {
            float m  = s * (1.0f / 128.0f);
            float vv = q * (1.0f / 128.0f) - m * m;
            float rv = rsqrtf(vv + 1e-5f);
            rs_s[r] = rv;
            rm_s[r] = -rv * m;
        }
    }
    if (tid < 128) { c1s[tid] = g_c1[tid]; c0s[tid] = g_c0[tid]; }
    __syncthreads();

    float acc[8][4];
#pragma unroll
    for (int nt = 0; nt < 8; ++nt)
#pragma unroll
        for (int j = 0; j < 4; ++j) acc[nt][j] = 0.f;

    const int l4 = lane >> 2, lm = lane & 3;
    const int rg = warp & 3, nh = warp >> 2;   // row-group / n-half
    const int R = rg * 16;
    unsigned ah_addr = smem_u32(Ah) + ((R + (lane & 15)) * AST + (lane >> 4) * 8) * 2;
    unsigned al_addr = smem_u32(Al) + ((R + (lane & 15)) * AST + (lane >> 4) * 8) * 2;

#pragma unroll
    for (int ks = 0; ks < 8; ++ks) {
        unsigned ah[4], al[4];
        ldsm4(ah, ah_addr + ks * 32);
        ldsm4(al, al_addr + ks * 32);
        const uint4* wf = g_wfrag + (size_t)nh * 8 * 256 + ks * 32 + lane;
#pragma unroll
        for (int nt = 0; nt < 8; ++nt) {
            uint4 f = wf[nt * 256];
            mma16816(acc[nt], ah, f.x, f.y);
            mma16816(acc[nt], al, f.x, f.y);
            mma16816(acc[nt], ah, f.z, f.w);
        }
    }
    int r0 = R + l4, r1 = r0 + 8;
    float rv0 = rs_s[r0], rm0 = rm_s[r0];
    float rv1 = rs_s[r1], rm1 = rm_s[r1];
    float* out0 = g_kv + (rowbase + r0) * 128;
    float* out1 = g_kv + (rowbase + r1) * 128;
#pragma unroll
    for (int nt = 0; nt < 8; ++nt) {
        int c = (nh * 8 + nt) * 8 + 2 * lm;
        float2 o0, o1;
        o0.x = rv0 * acc[nt][0] + rm0 * c1s[c]     + c0s[c];
        o0.y = rv0 * acc[nt][1] + rm0 * c1s[c + 1] + c0s[c + 1];
        o1.x = rv1 * acc[nt][2] + rm1 * c1s[c]     + c0s[c];
        o1.y = rv1 * acc[nt][3] + rm1 * c1s[c + 1] + c0s[c + 1];
        *(float2*)(out0 + c) = o0;
        *(float2*)(out1 + c) = o1;
    }
}

// ---------------- attention: direct-global k/v, q in registers, dedup (R13 version) ----------------
__global__ void __launch_bounds__(256, 2) kernel_attn()
{
    __shared__ float redU[16 * 512];   // 32KB
    __shared__ float redS[64];

    int tid = threadIdx.x, lane = tid & 31, warp = tid >> 5;
    int b = blockIdx.y, ch = blockIdx.x;
    const float* kv = g_kv + ((size_t)b * NN + ch * 128) * 128;

    const int tl = lane >> 3, c = lane & 7;   // token-in-group, col-segment/slot
    const int c8  = c * 8;
    const int hh  = tl >> 1;
    const int sgb = (tl & 1) * 4;

    // q segments: q[slot si][cols c8..c8+7] -> registers
    float4 qs[8][2];
    {
        const float4* qg = (const float4*)(g_q + b * 512);
#pragma unroll
        for (int si = 0; si < 8; ++si) {
            qs[si][0] = qg[si * 16 + c * 2];
            qs[si][1] = qg[si * 16 + c * 2 + 1];
        }
    }

    float4 U4[4][2];
#pragma unroll
    for (int j = 0; j < 4; ++j) {
        U4[j][0] = make_float4(0.f, 0.f, 0.f, 0.f);
        U4[j][1] = make_float4(0.f, 0.f, 0.f, 0.f);
    }
    float sacc = 0.f;

    for (int rd = 0; rd < 4; ++rd) {
        int tb = warp * 16 + rd * 4;

        const float* kp = kv + (tb + tl) * 128 + c8;
        float4 k0 = *(const float4*)(kp);
        float4 k1 = *(const float4*)(kp + 4);
        float part[8];
#pragma unroll
        for (int si = 0; si < 8; ++si)
            part[si] = d4(k0, qs[si][0]) + d4(k1, qs[si][1]);
        float p2[4];
#pragma unroll
        for (int i = 0; i < 4; ++i) {
            float send = (c & 4) ? part[i] : part[4 + i];
            float keep = (c & 4) ? part[4 + i] : part[i];
            p2[i] = keep + __shfl_xor_sync(0xffffffffu, send, 4);
        }
        float p3[2];
#pragma unroll
        for (int i = 0; i < 2; ++i) {
            float send = (c & 2) ? p2[i] : p2[2 + i];
            float keep = (c & 2) ? p2[2 + i] : p2[i];
            p3[i] = keep + __shfl_xor_sync(0xffffffffu, send, 2);
        }
        float sc;
        {
            float send = (c & 1) ? p3[0] : p3[1];
            float keep = (c & 1) ? p3[1] : p3[0];
            sc = keep + __shfl_xor_sync(0xffffffffu, send, 1);
        }
        sc *= 0.125f;  // H^-0.5

        float mx = sc;
        mx = fmaxf(mx, __shfl_xor_sync(0xffffffffu, mx, 1));
        mx = fmaxf(mx, __shfl_xor_sync(0xffffffffu, mx, 2));
        mx = fmaxf(mx, __shfl_xor_sync(0xffffffffu, mx, 4));
        float e  = expf(sc - mx);
        float se = e;
        se += __shfl_xor_sync(0xffffffffu, se, 1);
        se += __shfl_xor_sync(0xffffffffu, se, 2);
        se += __shfl_xor_sync(0xffffffffu, se, 4);
        float at = e / se + 1e-8f;   // attn[tb+tl][slot c]
        sacc += at;

#pragma unroll
        for (int tt2 = 0; tt2 < 2; ++tt2) {
            int tloc = 2 * hh + tt2;
            float a0 = __shfl_sync(0xffffffffu, at, (tloc << 3) + sgb + 0);
            float a1 = __shfl_sync(0xffffffffu, at, (tloc << 3) + sgb + 1);
            float a2 = __shfl_sync(0xffffffffu, at, (tloc << 3) + sgb + 2);
            float a3 = __shfl_sync(0xffffffffu, at, (tloc << 3) + sgb + 3);
            const float* vp = kv + (tb + tloc) * 128 + 64 + c8;
            float4 v0 = *(const float4*)(vp);
            float4 v1 = *(const float4*)(vp + 4);
            fma4(U4[0][0], a0, v0); fma4(U4[0][1], a0, v1);
            fma4(U4[1][0], a1, v0); fma4(U4[1][1], a1, v1);
            fma4(U4[2][0], a2, v0); fma4(U4[2][1], a2, v1);
            fma4(U4[3][0], a3, v0); fma4(U4[3][1], a3, v1);
        }
    }
    {
        float* ru = redU + (warp * 2 + hh) * 512;
#pragma unroll
        for (int j = 0; j < 4; ++j) {
            *(float4*)(ru + (sgb + j) * 64 + c8)     = U4[j][0];
            *(float4*)(ru + (sgb + j) * 64 + c8 + 4) = U4[j][1];
        }
    }
    sacc += __shfl_xor_sync(0xffffffffu, sacc, 8);
    sacc += __shfl_xor_sync(0xffffffffu, sacc, 16);
    if (tl == 0) redS[warp * 8 + c] = sacc;
    __syncthreads();

    int obase = b * NCH + ch;
    for (int idx = tid; idx < 512; idx += 256) {
        float t = 0.f;
#pragma unroll
        for (int w = 0; w < 16; ++w) t += redU[w * 512 + idx];
        g_partU[obase * 512 + idx] = t;
    }
    if (tid < 8) {
        float t = 0.f;
#pragma unroll
        for (int w = 0; w < 8; ++w) t += redS[w * 8 + tid];
        g_partS[obase * 8 + tid] = t;
    }
}

// ---------------- finalize: block per (batch, slot-pair), 256 threads ----------------
__global__ void __launch_bounds__(256) kernel_final(
    const float* __restrict__ wih, const float* __restrict__ whh,
    const float* __restrict__ bih, const float* __restrict__ bhh,
    const float* __restrict__ w1,  const float* __restrict__ b1,
    const float* __restrict__ w2,  const float* __restrict__ b2,
    const float* __restrict__ gml, const float* __restrict__ bml,
    const float* __restrict__ gsl, const float* __restrict__ bsl,
    const float* __restrict__ Wq, float* __restrict__ out, int last)
{
    __shared__ float red[256];
    __shared__ float sm_u[128], sm_h[128];   // [sl][64]
    __shared__ float sm_g[768];              // [gate_row][sl]
    __shared__ float sm_t[128];
    __shared__ float sm_hid[256];            // [sl][128]
    __shared__ float sm_ns[128];
    __shared__ float sm_S[2];

    const int t = threadIdx.x, lane = t & 31, warp = t >> 5;
    const int blk = blockIdx.x, b = blk >> 2, s0 = (blk & 3) * 2;   // slots s0, s0+1

    {
        int e = t & 127, half = t >> 7;
        int sl = e >> 6, h = e & 63;
        const float* pu = g_partU + (size_t)b * NCH * 512 + (s0 + sl) * 64 + h;
        float acc = 0.f;
#pragma unroll
        for (int cc = 0; cc < 16; ++cc) acc += pu[(half * 16 + cc) * 512];
        red[t] = acc;
    }
    if (warp < 2) {
        float sv = g_partS[(b * NCH + lane) * 8 + s0 + warp];
#pragma unroll
        for (int o = 16; o; o >>= 1) sv += __shfl_xor_sync(0xffffffffu, sv, o);
        if (lane == 0) sm_S[warp] = sv;
    }
    __syncthreads();
    if (t < 128) {
        float U = red[t] + red[t + 128];
        sm_u[t] = U / sm_S[t >> 6];
        sm_h[t] = g_slots[b * 512 + (s0 + (t >> 6)) * 64 + (t & 63)];
    }
    __syncthreads();

#pragma unroll
    for (int rep = 0; rep < 2; ++rep) {
        int row = t + rep * 256;
        if (rep == 1 && t >= 128) break;
        const float* wrow = (row < 192) ? (wih + row * 64) : (whh + (size_t)(row - 192) * 64);
        const float* inp  = (row < 192) ? sm_u : sm_h;
        float bias = (row < 192) ? bih[row] : bhh[row - 192];
        float a0 = bias, a1 = bias;
#pragma unroll
        for (int j = 0; j < 16; ++j) {
            float4 w = *(const float4*)(wrow + 4 * j);
            a0 += d4(w, *(const float4*)(inp + 4 * j));
            a1 += d4(w, *(const float4*)(inp + 64 + 4 * j));
        }
        sm_g[row * 2 + 0] = a0;
        sm_g[row * 2 + 1] = a1;
    }
    __syncthreads();

    if (t < 128) {
        int sl = t >> 6, h = t & 63;
        float r = sigf(sm_g[h * 2 + sl]         + sm_g[(192 + h) * 2 + sl]);
        float z = sigf(sm_g[(64 + h) * 2 + sl]  + sm_g[(256 + h) * 2 + sl]);
        float n = tanhf(sm_g[(128 + h) * 2 + sl] + r * sm_g[(320 + h) * 2 + sl]);
        sm_ns[t] = (1.f - z) * n + z * sm_h[t];
    }
    __syncthreads();
    if (warp < 2) {
        float v0 = sm_ns[warp * 64 + lane], v1 = sm_ns[warp * 64 + lane + 32];
        ln64_reg(v0, v1, gml, bml, lane);
        sm_t[warp * 64 + lane] = v0;
        sm_t[warp * 64 + lane + 32] = v1;
    }
    __syncthreads();

    if (t < 128) {
        float a0 = b1[t], a1 = a0;
        const float* wrow = w1 + t * 64;
#pragma unroll
        for (int j = 0; j < 16; ++j) {
            float4 w = *(const float4*)(wrow + 4 * j);
            a0 += d4(w, *(const float4*)(sm_t + 4 * j));
            a1 += d4(w, *(const float4*)(sm_t + 64 + 4 * j));
        }
        sm_hid[t]       = fmaxf(a0, 0.f);
        sm_hid[128 + t] = fmaxf(a1, 0.f);
    }
    __syncthreads();

    if (t < 128) {
        int row = t >> 1, half = t & 1;
        float a0 = half ? 0.f : b2[row], a1 = a0;
        const float* wrow = w2 + row * 128 + half * 64;
        const float* i0 = sm_hid + half * 64;
        const float* i1 = sm_hid + 128 + half * 64;
#pragma unroll
        for (int j = 0; j < 16; ++j) {
            float4 w = *(const float4*)(wrow + 4 * j);
            a0 += d4(w, *(const float4*)(i0 + 4 * j));
            a1 += d4(w, *(const float4*)(i1 + 4 * j));
        }
        a0 += __shfl_xor_sync(0xffffffffu, a0, 1);
        a1 += __shfl_xor_sync(0xffffffffu, a1, 1);
        if (!half) {
            float n0 = sm_t[row] + a0;
            float n1 = sm_t[64 + row] + a1;
            g_slots[b * 512 + s0 * 64 + row] = n0;
            g_slots[b * 512 + (s0 + 1) * 64 + row] = n1;
            if (last) {
                out[b * 512 + s0 * 64 + row] = n0;
                out[b * 512 + (s0 + 1) * 64 + row] = n1;
            }
            sm_ns[row] = n0;
            sm_ns[64 + row] = n1;
        }
    }
    __syncthreads();
    if (!last) {
        if (warp < 2) {
            float v0 = sm_ns[warp * 64 + lane], v1 = sm_ns[warp * 64 + lane + 32];
            ln64_reg(v0, v1, gsl, bsl, lane);
            sm_t[warp * 64 + lane] = v0;
            sm_t[warp * 64 + lane + 32] = v1;
        }
        __syncthreads();
        if (t < 128) {
            int row = t >> 1, half = t & 1;
            float a0 = 0.f, a1 = 0.f;
            const float* wrow = Wq + row * 64 + half * 32;
#pragma unroll
            for (int j = 0; j < 8; ++j) {
                float4 w = *(const float4*)(wrow + 4 * j);
                a0 += d4(w, *(const float4*)(sm_t + half * 32 + 4 * j));
                a1 += d4(w, *(const float4*)(sm_t + 64 + half * 32 + 4 * j));
            }
            a0 += __shfl_xor_sync(0xffffffffu, a0, 1);
            a1 += __shfl_xor_sync(0xffffffffu, a1, 1);
            if (!half) {
                g_q[b * 512 + s0 * 64 + row] = a0;
                g_q[b * 512 + (s0 + 1) * 64 + row] = a1;
            }
        }
    }
}

// ---------------- launch ----------------
extern "C" void kernel_launch(void* const* d_in, const int* in_sizes, int n_in,
                              void* d_out, int out_size)
{
    const float* x       = (const float*)d_in[0];
    const float* noise   = (const float*)d_in[1];
    const float* Wq      = (const float*)d_in[2];
    const float* Wk      = (const float*)d_in[3];
    const float* Wv      = (const float*)d_in[4];
    const float* ln_in_g = (const float*)d_in[5];
    const float* ln_in_b = (const float*)d_in[6];
    const float* ln_sl_g = (const float*)d_in[7];
    const float* ln_sl_b = (const float*)d_in[8];
    const float* ln_ml_g = (const float*)d_in[9];
    const float* ln_ml_b = (const float*)d_in[10];
    const float* gru_wih = (const float*)d_in[11];
    const float* gru_whh = (const float*)d_in[12];
    const float* gru_bih = (const float*)d_in[13];
    const float* gru_bhh = (const float*)d_in[14];
    const float* mlp_w1  = (const float*)d_in[15];
    const float* mlp_b1  = (const float*)d_in[16];
    const float* mlp_w2  = (const float*)d_in[17];
    const float* mlp_b2  = (const float*)d_in[18];
    const float* mu      = (const float*)d_in[19];
    const float* ls      = (const float*)d_in[20];
    float* out = (float*)d_out;

    // 4 pack launches + slots => gemm is launch #6 (ncu -s 5 -c 1 captures it)
    for (int i = 0; i < 4; ++i)
        kernel_pack<<<4, 256>>>(Wk, Wv, ln_in_g, ln_in_b, i * 4);
    kernel_slots<<<NB, 256>>>(noise, mu, ls, ln_sl_g, ln_sl_b, Wq);
    kernel_gemm<<<(NB * NN) / 64, 256>>>(x);
    for (int it = 0; it < 3; ++it) {
        kernel_attn<<<dim3(NCH, NB), 256>>>();
        kernel_final<<<NB * 4, 256>>>(gru_wih, gru_whh, gru_bih, gru_bhh,
                                      mlp_w1, mlp_b1, mlp_w2, mlp_b2,
                                      ln_ml_g, ln_ml_b, ln_sl_g, ln_sl_b,
                                      Wq, out, it == 2 ? 1 : 0);
    }
}

// round 17
// speedup vs baseline: 1.4899x; 1.0405x over previous
#include <cuda_runtime.h>
#include <cuda_bf16.h>
#include <math.h>

#define NB 32
#define NN 4096
#define DD 128
#define HH 64
#define KK 8
#define NCH 32          // token chunks per batch (4096/128)
#define AST 136         // gemm smem stride (bf16 elems), conflict-free

// ---------------- device scratch ----------------
__device__ __align__(16) float g_kv[(size_t)NB * NN * DD];   // [row][0..63]=k, [64..127]=v
__device__ __align__(16) float g_partU[NB * NCH * KK * HH];
__device__ __align__(16) float g_partS[NB * NCH * KK];
__device__ __align__(16) float g_slots[NB * KK * HH];
__device__ __align__(16) float g_q[NB * KK * HH];
__device__ __align__(16) uint4 g_wfrag[16 * 8 * 32];         // fragment-ordered g∘[Wk;Wv] hi/lo
__device__ __align__(16) float g_c1[128];
__device__ __align__(16) float g_c0[128];

// ---------------- helpers ----------------
__device__ __forceinline__ float d4(float4 a, float4 b) {
    return a.x * b.x + a.y * b.y + a.z * b.z + a.w * b.w;
}
__device__ __forceinline__ void fma4(float4& u, float a, float4 v) {
    u.x += a * v.x; u.y += a * v.y; u.z += a * v.z; u.w += a * v.w;
}
__device__ __forceinline__ unsigned packbf(float a, float b) {
    __nv_bfloat162 t;
    t.x = __float2bfloat16(a);
    t.y = __float2bfloat16(b);
    return *reinterpret_cast<unsigned*>(&t);
}
__device__ __forceinline__ void mma16816(float (&d)[4], const unsigned (&a)[4],
                                         unsigned b0, unsigned b1) {
    asm volatile(
        "mma.sync.aligned.m16n8k16.row.col.f32.bf16.bf16.f32 "
        "{%0,%1,%2,%3},{%4,%5,%6,%7},{%8,%9},{%0,%1,%2,%3};\n"
        : "+f"(d[0]), "+f"(d[1]), "+f"(d[2]), "+f"(d[3])
        : "r"(a[0]), "r"(a[1]), "r"(a[2]), "r"(a[3]), "r"(b0), "r"(b1));
}
__device__ __forceinline__ void ldsm4(unsigned (&r)[4], unsigned addr) {
    asm volatile("ldmatrix.sync.aligned.m8n8.x4.shared.b16 {%0,%1,%2,%3}, [%4];"
                 : "=r"(r[0]), "=r"(r[1]), "=r"(r[2]), "=r"(r[3]) : "r"(addr));
}
__device__ __forceinline__ unsigned smem_u32(const void* p) {
    unsigned a;
    asm("{ .reg .u64 t; cvta.to.shared.u64 t, %1; cvt.u32.u64 %0, t; }" : "=r"(a) : "l"(p));
    return a;
}
__device__ __forceinline__ float sigf(float x) { return 1.0f / (1.0f + expf(-x)); }

// LayerNorm over 64 elems held as (v0=idx lane, v1=idx lane+32) by one warp, eps=1e-5
__device__ __forceinline__ void ln64_reg(float& v0, float& v1,
                                         const float* __restrict__ g,
                                         const float* __restrict__ bb, int lane) {
    float s = v0 + v1, ss = v0 * v0 + v1 * v1;
#pragma unroll
    for (int o = 16; o; o >>= 1) {
        s  += __shfl_xor_sync(0xffffffffu, s,  o);
        ss += __shfl_xor_sync(0xffffffffu, ss, o);
    }
    float m  = s * (1.0f / 64.0f);
    float vv = ss * (1.0f / 64.0f) - m * m;
    float rs = rsqrtf(vv + 1e-5f);
    v0 = (v0 - m) * rs * g[lane]      + bb[lane];
    v1 = (v1 - m) * rs * g[lane + 32] + bb[lane + 32];
}

// ---------------- init: W pack (blocks NB..NB+15) + slots init + q0 (blocks 0..NB-1) ----------------
__global__ void __launch_bounds__(256) kernel_init(
    const float* __restrict__ Wk, const float* __restrict__ Wv,
    const float* __restrict__ ln_in_g, const float* __restrict__ ln_in_b,
    const float* __restrict__ noise,
    const float* __restrict__ mu, const float* __restrict__ ls,
    const float* __restrict__ gsl, const float* __restrict__ bsl,
    const float* __restrict__ Wq)
{
    int tid = threadIdx.x, lane = tid & 31;
    if (blockIdx.x >= NB) {
        int p = (blockIdx.x - NB) * 8 + (tid >> 5);   // 0..127
        {
            const float* wrow = (p < 64) ? (Wk + p * 128) : (Wv + (size_t)(p - 64) * 128);
            float c1 = 0.f, c0 = 0.f;
#pragma unroll
            for (int i = 0; i < 4; ++i) {
                int d = lane + i * 32;
                float w = wrow[d];
                c1 += w * ln_in_g[d];
                c0 += ln_in_b[d] * w;
            }
#pragma unroll
            for (int o = 16; o; o >>= 1) {
                c1 += __shfl_xor_sync(0xffffffffu, c1, o);
                c0 += __shfl_xor_sync(0xffffffffu, c0, o);
            }
            if (lane == 0) { g_c1[p] = c1; g_c0[p] = c0; }
        }
        {
            int r2 = (p >> 3) * 8 + (lane >> 2);          // W row (output col n)
            int cc = (p & 7) * 16 + 2 * (lane & 3);       // k column base
            const float* wr = (r2 < 64) ? (Wk + r2 * 128) : (Wv + (size_t)(r2 - 64) * 128);
            float w0 = wr[cc]     * ln_in_g[cc];
            float w1 = wr[cc + 1] * ln_in_g[cc + 1];
            float w8 = wr[cc + 8] * ln_in_g[cc + 8];
            float w9 = wr[cc + 9] * ln_in_g[cc + 9];
            __nv_bfloat16 h0 = __float2bfloat16(w0), h1 = __float2bfloat16(w1);
            __nv_bfloat16 h8 = __float2bfloat16(w8), h9 = __float2bfloat16(w9);
            uint4 f;
            f.x = packbf(__bfloat162float(h0), __bfloat162float(h1));
            f.y = packbf(__bfloat162float(h8), __bfloat162float(h9));
            f.z = packbf(w0 - __bfloat162float(h0), w1 - __bfloat162float(h1));
            f.w = packbf(w8 - __bfloat162float(h8), w9 - __bfloat162float(h9));
            g_wfrag[p * 32 + lane] = f;
        }
        return;
    }
    int b = blockIdx.x;
    __shared__ float sl[512], tq[512];
    for (int idx = tid; idx < 512; idx += 256) {
        float scale = log1pf(expf(ls[idx])) + 1e-5f;   // softplus + 1e-5
        float v = mu[idx] + scale * noise[b * 512 + idx];
        sl[idx] = v;
        g_slots[b * 512 + idx] = v;
    }
    __syncthreads();
    int s = tid >> 5;
    float v0 = sl[s * 64 + lane], v1 = sl[s * 64 + lane + 32];
    ln64_reg(v0, v1, gsl, bsl, lane);
    tq[s * 64 + lane] = v0;
    tq[s * 64 + lane + 32] = v1;
    __syncwarp();
    float q0 = 0.f, q1 = 0.f;
#pragma unroll
    for (int j = 0; j < 16; ++j) {
        float4 t4 = *(const float4*)&tq[s * 64 + 4 * j];
        q0 += d4(*(const float4*)(Wq + lane * 64 + 4 * j), t4);
        q1 += d4(*(const float4*)(Wq + (lane + 32) * 64 + 4 * j), t4);
    }
    g_q[b * 512 + s * 64 + lane] = q0;
    g_q[b * 512 + s * 64 + lane + 32] = q1;
}

// ---------------- GEMM: BM=64 tile, warp-split-N, ldmatrix A + fragment-table W ----------------
__global__ void __launch_bounds__(256) kernel_gemm(const float* __restrict__ x)
{
    __shared__ __nv_bfloat16 Ah[64 * AST];
    __shared__ __nv_bfloat16 Al[64 * AST];
    __shared__ float rs_s[64], rm_s[64], c1s[128], c0s[128];

    int tid = threadIdx.x, lane = tid & 31, warp = tid >> 5;
    size_t rowbase = (size_t)blockIdx.x * 64;

    for (int i = 0; i < 8; ++i) {
        int r = i * 8 + warp;
        float4 xv = *(const float4*)(x + (rowbase + r) * 128 + lane * 4);
        float s = xv.x + xv.y + xv.z + xv.w;
        float q = xv.x * xv.x + xv.y * xv.y + xv.z * xv.z + xv.w * xv.w;
#pragma unroll
        for (int o = 16; o; o >>= 1) {
            s += __shfl_xor_sync(0xffffffffu, s, o);
            q += __shfl_xor_sync(0xffffffffu, q, o);
        }
        __nv_bfloat16 h0 = __float2bfloat16(xv.x), h1 = __float2bfloat16(xv.y);
        __nv_bfloat16 h2 = __float2bfloat16(xv.z), h3 = __float2bfloat16(xv.w);
        *(unsigned*)(Ah + r * AST + lane * 4)     = packbf(xv.x, xv.y);
        *(unsigned*)(Ah + r * AST + lane * 4 + 2) = packbf(xv.z, xv.w);
        *(unsigned*)(Al + r * AST + lane * 4)     =
            packbf(xv.x - __bfloat162float(h0), xv.y - __bfloat162float(h1));
        *(unsigned*)(Al + r * AST + lane * 4 + 2) =
            packbf(xv.z - __bfloat162float(h2), xv.w - __bfloat162float(h3));
        if (lane == 0) {
            float m  = s * (1.0f / 128.0f);
            float vv = q * (1.0f / 128.0f) - m * m;
            float rv = rsqrtf(vv + 1e-5f);
            rs_s[r] = rv;
            rm_s[r] = -rv * m;
        }
    }
    if (tid < 128) { c1s[tid] = g_c1[tid]; c0s[tid] = g_c0[tid]; }
    __syncthreads();

    float acc[8][4];
#pragma unroll
    for (int nt = 0; nt < 8; ++nt)
#pragma unroll
        for (int j = 0; j < 4; ++j) acc[nt][j] = 0.f;

    const int l4 = lane >> 2, lm = lane & 3;
    const int rg = warp & 3, nh = warp >> 2;   // row-group / n-half
    const int R = rg * 16;
    unsigned ah_addr = smem_u32(Ah) + ((R + (lane & 15)) * AST + (lane >> 4) * 8) * 2;
    unsigned al_addr = smem_u32(Al) + ((R + (lane & 15)) * AST + (lane >> 4) * 8) * 2;

#pragma unroll
    for (int ks = 0; ks < 8; ++ks) {
        unsigned ah[4], al[4];
        ldsm4(ah, ah_addr + ks * 32);
        ldsm4(al, al_addr + ks * 32);
        const uint4* wf = g_wfrag + (size_t)nh * 8 * 256 + ks * 32 + lane;
#pragma unroll
        for (int nt = 0; nt < 8; ++nt) {
            uint4 f = wf[nt * 256];
            mma16816(acc[nt], ah, f.x, f.y);
            mma16816(acc[nt], al, f.x, f.y);
            mma16816(acc[nt], ah, f.z, f.w);
        }
    }
    int r0 = R + l4, r1 = r0 + 8;
    float rv0 = rs_s[r0], rm0 = rm_s[r0];
    float rv1 = rs_s[r1], rm1 = rm_s[r1];
    float* out0 = g_kv + (rowbase + r0) * 128;
    float* out1 = g_kv + (rowbase + r1) * 128;
#pragma unroll
    for (int nt = 0; nt < 8; ++nt) {
        int c = (nh * 8 + nt) * 8 + 2 * lm;
        float2 o0, o1;
        o0.x = rv0 * acc[nt][0] + rm0 * c1s[c]     + c0s[c];
        o0.y = rv0 * acc[nt][1] + rm0 * c1s[c + 1] + c0s[c + 1];
        o1.x = rv1 * acc[nt][2] + rm1 * c1s[c]     + c0s[c];
        o1.y = rv1 * acc[nt][3] + rm1 * c1s[c + 1] + c0s[c + 1];
        *(float2*)(out0 + c) = o0;
        *(float2*)(out1 + c) = o1;
    }
}

// ---------------- attention: direct-global k/v, q in registers, dedup ----------------
__global__ void __launch_bounds__(256, 2) kernel_attn()
{
    __shared__ float redU[16 * 512];   // 32KB
    __shared__ float redS[64];

    int tid = threadIdx.x, lane = tid & 31, warp = tid >> 5;
    int b = blockIdx.y, ch = blockIdx.x;
    const float* kv = g_kv + ((size_t)b * NN + ch * 128) * 128;

    const int tl = lane >> 3, c = lane & 7;   // token-in-group, col-segment/slot
    const int c8  = c * 8;
    const int hh  = tl >> 1;
    const int sgb = (tl & 1) * 4;

    float4 qs[8][2];
    {
        const float4* qg = (const float4*)(g_q + b * 512);
#pragma unroll
        for (int si = 0; si < 8; ++si) {
            qs[si][0] = qg[si * 16 + c * 2];
            qs[si][1] = qg[si * 16 + c * 2 + 1];
        }
    }

    float4 U4[4][2];
#pragma unroll
    for (int j = 0; j < 4; ++j) {
        U4[j][0] = make_float4(0.f, 0.f, 0.f, 0.f);
        U4[j][1] = make_float4(0.f, 0.f, 0.f, 0.f);
    }
    float sacc = 0.f;

    for (int rd = 0; rd < 4; ++rd) {
        int tb = warp * 16 + rd * 4;

        const float* kp = kv + (tb + tl) * 128 + c8;
        float4 k0 = *(const float4*)(kp);
        float4 k1 = *(const float4*)(kp + 4);
        float part[8];
#pragma unroll
        for (int si = 0; si < 8; ++si)
            part[si] = d4(k0, qs[si][0]) + d4(k1, qs[si][1]);
        float p2[4];
#pragma unroll
        for (int i = 0; i < 4; ++i) {
            float send = (c & 4) ? part[i] : part[4 + i];
            float keep = (c & 4) ? part[4 + i] : part[i];
            p2[i] = keep + __shfl_xor_sync(0xffffffffu, send, 4);
        }
        float p3[2];
#pragma unroll
        for (int i = 0; i < 2; ++i) {
            float send = (c & 2) ? p2[i] : p2[2 + i];
            float keep = (c & 2) ? p2[2 + i] : p2[i];
            p3[i] = keep + __shfl_xor_sync(0xffffffffu, send, 2);
        }
        float sc;
        {
            float send = (c & 1) ? p3[0] : p3[1];
            float keep = (c & 1) ? p3[1] : p3[0];
            sc = keep + __shfl_xor_sync(0xffffffffu, send, 1);
        }
        sc *= 0.125f;  // H^-0.5

        float mx = sc;
        mx = fmaxf(mx, __shfl_xor_sync(0xffffffffu, mx, 1));
        mx = fmaxf(mx, __shfl_xor_sync(0xffffffffu, mx, 2));
        mx = fmaxf(mx, __shfl_xor_sync(0xffffffffu, mx, 4));
        float e  = expf(sc - mx);
        float se = e;
        se += __shfl_xor_sync(0xffffffffu, se, 1);
        se += __shfl_xor_sync(0xffffffffu, se, 2);
        se += __shfl_xor_sync(0xffffffffu, se, 4);
        float at = e / se + 1e-8f;   // attn[tb+tl][slot c]
        sacc += at;

#pragma unroll
        for (int tt2 = 0; tt2 < 2; ++tt2) {
            int tloc = 2 * hh + tt2;
            float a0 = __shfl_sync(0xffffffffu, at, (tloc << 3) + sgb + 0);
            float a1 = __shfl_sync(0xffffffffu, at, (tloc << 3) + sgb + 1);
            float a2 = __shfl_sync(0xffffffffu, at, (tloc << 3) + sgb + 2);
            float a3 = __shfl_sync(0xffffffffu, at, (tloc << 3) + sgb + 3);
            const float* vp = kv + (tb + tloc) * 128 + 64 + c8;
            float4 v0 = *(const float4*)(vp);
            float4 v1 = *(const float4*)(vp + 4);
            fma4(U4[0][0], a0, v0); fma4(U4[0][1], a0, v1);
            fma4(U4[1][0], a1, v0); fma4(U4[1][1], a1, v1);
            fma4(U4[2][0], a2, v0); fma4(U4[2][1], a2, v1);
            fma4(U4[3][0], a3, v0); fma4(U4[3][1], a3, v1);
        }
    }
    {
        float* ru = redU + (warp * 2 + hh) * 512;
#pragma unroll
        for (int j = 0; j < 4; ++j) {
            *(float4*)(ru + (sgb + j) * 64 + c8)     = U4[j][0];
            *(float4*)(ru + (sgb + j) * 64 + c8 + 4) = U4[j][1];
        }
    }
    sacc += __shfl_xor_sync(0xffffffffu, sacc, 8);
    sacc += __shfl_xor_sync(0xffffffffu, sacc, 16);
    if (tl == 0) redS[warp * 8 + c] = sacc;
    __syncthreads();

    int obase = b * NCH + ch;
    for (int idx = tid; idx < 512; idx += 256) {
        float t = 0.f;
#pragma unroll
        for (int w = 0; w < 16; ++w) t += redU[w * 512 + idx];
        g_partU[obase * 512 + idx] = t;
    }
    if (tid < 8) {
        float t = 0.f;
#pragma unroll
        for (int w = 0; w < 8; ++w) t += redS[w * 8 + tid];
        g_partS[obase * 8 + tid] = t;
    }
}

// ---------------- finalize: block per (batch, slot-pair), 256 threads ----------------
__global__ void __launch_bounds__(256) kernel_final(
    const float* __restrict__ wih, const float* __restrict__ whh,
    const float* __restrict__ bih, const float* __restrict__ bhh,
    const float* __restrict__ w1,  const float* __restrict__ b1,
    const float* __restrict__ w2,  const float* __restrict__ b2,
    const float* __restrict__ gml, const float* __restrict__ bml,
    const float* __restrict__ gsl, const float* __restrict__ bsl,
    const float* __restrict__ Wq, float* __restrict__ out, int last)
{
    __shared__ float red[256];
    __shared__ float sm_u[128], sm_h[128];   // [sl][64]
    __shared__ float sm_g[768];              // [gate_row][sl]
    __shared__ float sm_t[128];
    __shared__ float sm_hid[256];            // [sl][128]
    __shared__ float sm_ns[128];
    __shared__ float sm_S[2];

    const int t = threadIdx.x, lane = t & 31, warp = t >> 5;
    const int blk = blockIdx.x, b = blk >> 2, s0 = (blk & 3) * 2;   // slots s0, s0+1

    {
        int e = t & 127, half = t >> 7;
        int sl = e >> 6, h = e & 63;
        const float* pu = g_partU + (size_t)b * NCH * 512 + (s0 + sl) * 64 + h;
        float acc = 0.f;
#pragma unroll
        for (int cc = 0; cc < 16; ++cc) acc += pu[(half * 16 + cc) * 512];
        red[t] = acc;
    }
    if (warp < 2) {
        float sv = g_partS[(b * NCH + lane) * 8 + s0 + warp];
#pragma unroll
        for (int o = 16; o; o >>= 1) sv += __shfl_xor_sync(0xffffffffu, sv, o);
        if (lane == 0) sm_S[warp] = sv;
    }
    __syncthreads();
    if (t < 128) {
        float U = red[t] + red[t + 128];
        sm_u[t] = U / sm_S[t >> 6];
        sm_h[t] = g_slots[b * 512 + (s0 + (t >> 6)) * 64 + (t & 63)];
    }
    __syncthreads();

#pragma unroll
    for (int rep = 0; rep < 2; ++rep) {
        int row = t + rep * 256;
        if (rep == 1 && t >= 128) break;
        const float* wrow = (row < 192) ? (wih + row * 64) : (whh + (size_t)(row - 192) * 64);
        const float* inp  = (row < 192) ? sm_u : sm_h;
        float bias = (row < 192) ? bih[row] : bhh[row - 192];
        float a0 = bias, a1 = bias;
#pragma unroll
        for (int j = 0; j < 16; ++j) {
            float4 w = *(const float4*)(wrow + 4 * j);
            a0 += d4(w, *(const float4*)(inp + 4 * j));
            a1 += d4(w, *(const float4*)(inp + 64 + 4 * j));
        }
        sm_g[row * 2 + 0] = a0;
        sm_g[row * 2 + 1] = a1;
    }
    __syncthreads();

    if (t < 128) {
        int sl = t >> 6, h = t & 63;
        float r = sigf(sm_g[h * 2 + sl]         + sm_g[(192 + h) * 2 + sl]);
        float z = sigf(sm_g[(64 + h) * 2 + sl]  + sm_g[(256 + h) * 2 + sl]);
        float n = tanhf(sm_g[(128 + h) * 2 + sl] + r * sm_g[(320 + h) * 2 + sl]);
        sm_ns[t] = (1.f - z) * n + z * sm_h[t];
    }
    __syncthreads();
    if (warp < 2) {
        float v0 = sm_ns[warp * 64 + lane], v1 = sm_ns[warp * 64 + lane + 32];
        ln64_reg(v0, v1, gml, bml, lane);
        sm_t[warp * 64 + lane] = v0;
        sm_t[warp * 64 + lane + 32] = v1;
    }
    __syncthreads();

    if (t < 128) {
        float a0 = b1[t], a1 = a0;
        const float* wrow = w1 + t * 64;
#pragma unroll
        for (int j = 0; j < 16; ++j) {
            float4 w = *(const float4*)(wrow + 4 * j);
            a0 += d4(w, *(const float4*)(sm_t + 4 * j));
            a1 += d4(w, *(const float4*)(sm_t + 64 + 4 * j));
        }
        sm_hid[t]       = fmaxf(a0, 0.f);
        sm_hid[128 + t] = fmaxf(a1, 0.f);
    }
    __syncthreads();

    if (t < 128) {
        int row = t >> 1, half = t & 1;
        float a0 = half ? 0.f : b2[row], a1 = a0;
        const float* wrow = w2 + row * 128 + half * 64;
        const float* i0 = sm_hid + half * 64;
        const float* i1 = sm_hid + 128 + half * 64;
#pragma unroll
        for (int j = 0; j < 16; ++j) {
            float4 w = *(const float4*)(wrow + 4 * j);
            a0 += d4(w, *(const float4*)(i0 + 4 * j));
            a1 += d4(w, *(const float4*)(i1 + 4 * j));
        }
        a0 += __shfl_xor_sync(0xffffffffu, a0, 1);
        a1 += __shfl_xor_sync(0xffffffffu, a1, 1);
        if (!half) {
            float n0 = sm_t[row] + a0;
            float n1 = sm_t[64 + row] + a1;
            g_slots[b * 512 + s0 * 64 + row] = n0;
            g_slots[b * 512 + (s0 + 1) * 64 + row] = n1;
            if (last) {
                out[b * 512 + s0 * 64 + row] = n0;
                out[b * 512 + (s0 + 1) * 64 + row] = n1;
            }
            sm_ns[row] = n0;
            sm_ns[64 + row] = n1;
        }
    }
    __syncthreads();
    if (!last) {
        if (warp < 2) {
            float v0 = sm_ns[warp * 64 + lane], v1 = sm_ns[warp * 64 + lane + 32];
            ln64_reg(v0, v1, gsl, bsl, lane);
            sm_t[warp * 64 + lane] = v0;
            sm_t[warp * 64 + lane + 32] = v1;
        }
        __syncthreads();
        if (t < 128) {
            int row = t >> 1, half = t & 1;
            float a0 = 0.f, a1 = 0.f;
            const float* wrow = Wq + row * 64 + half * 32;
#pragma unroll
            for (int j = 0; j < 8; ++j) {
                float4 w = *(const float4*)(wrow + 4 * j);
                a0 += d4(w, *(const float4*)(sm_t + half * 32 + 4 * j));
                a1 += d4(w, *(const float4*)(sm_t + 64 + half * 32 + 4 * j));
            }
            a0 += __shfl_xor_sync(0xffffffffu, a0, 1);
            a1 += __shfl_xor_sync(0xffffffffu, a1, 1);
            if (!half) {
                g_q[b * 512 + s0 * 64 + row] = a0;
                g_q[b * 512 + (s0 + 1) * 64 + row] = a1;
            }
        }
    }
}

// ---------------- launch ----------------
extern "C" void kernel_launch(void* const* d_in, const int* in_sizes, int n_in,
                              void* d_out, int out_size)
{
    const float* x       = (const float*)d_in[0];
    const float* noise   = (const float*)d_in[1];
    const float* Wq      = (const float*)d_in[2];
    const float* Wk      = (const float*)d_in[3];
    const float* Wv      = (const float*)d_in[4];
    const float* ln_in_g = (const float*)d_in[5];
    const float* ln_in_b = (const float*)d_in[6];
    const float* ln_sl_g = (const float*)d_in[7];
    const float* ln_sl_b = (const float*)d_in[8];
    const float* ln_ml_g = (const float*)d_in[9];
    const float* ln_ml_b = (const float*)d_in[10];
    const float* gru_wih = (const float*)d_in[11];
    const float* gru_whh = (const float*)d_in[12];
    const float* gru_bih = (const float*)d_in[13];
    const float* gru_bhh = (const float*)d_in[14];
    const float* mlp_w1  = (const float*)d_in[15];
    const float* mlp_b1  = (const float*)d_in[16];
    const float* mlp_w2  = (const float*)d_in[17];
    const float* mlp_b2  = (const float*)d_in[18];
    const float* mu      = (const float*)d_in[19];
    const float* ls      = (const float*)d_in[20];
    float* out = (float*)d_out;

    kernel_init<<<NB + 16, 256>>>(Wk, Wv, ln_in_g, ln_in_b, noise, mu, ls,
                                  ln_sl_g, ln_sl_b, Wq);
    kernel_gemm<<<(NB * NN) / 64, 256>>>(x);
    for (int it = 0; it < 3; ++it) {
        kernel_attn<<<dim3(NCH, NB), 256>>>();
        kernel_final<<<NB * 4, 256>>>(gru_wih, gru_whh, gru_bih, gru_bhh,
                                      mlp_w1, mlp_b1, mlp_w2, mlp_b2,
                                      ln_ml_g, ln_ml_b, ln_sl_g, ln_sl_b,
                                      Wq, out, it == 2 ? 1 : 0);
    }
}